// round 8
// baseline (speedup 1.0000x reference)
#include <cuda_runtime.h>
#include <math_constants.h>

// RankingLoss over all pairs, N=8192.
// loss = sum_{i,j: dur_i<dur_j, ev_i==1} max(1-(p_i-p_j),0) / count (0 if count==0).
//
// 3 kernels: (1) duration histogram + last-block exclusive prefix,
// (2) deterministic stable counting-sort scatter into g_sorted (by 64 duration bins),
// (3) tiled pair kernel with runtime full/skip/compare classification per block
//     (correct for ANY permutation; sort makes ~half the blocks skip and most of
//      the rest take the 3-instr/pair "all pairs valid" path). Last-arriving block
// reduces all partials in fixed order and writes the output.

#define NN   8192
#define BINS 64
#define HB   16                  // histogram/scatter blocks
#define HT   512                 // their threads
#define TPB  256
#define IG   512                 // i-rows per pair-block
#define JC   128                 // j-cols per pair-block
#define GX   (NN / JC)           // 64
#define GYI  (NN / IG)           // 16
#define NBLK (GX * GYI)          // 1024
#define NW   (TPB / 32)

__device__ float4       g_sorted[NN];        // {dur, pred, event, 0} duration-ordered
__device__ int          g_hist[BINS * HB];
__device__ int          g_offs[BINS * HB];
__device__ float        g_s[NBLK];
__device__ unsigned int g_c[NBLK];
__device__ unsigned int g_tick1 = 0u;
__device__ unsigned int g_tick2 = 0u;

__device__ __forceinline__ int dbin(float d) {
    int b = (int)(d * (float)BINS);          // monotone in d
    return b < 0 ? 0 : (b > BINS - 1 ? BINS - 1 : b);
}

// ---------------- kernel 1: histogram + (last block) exclusive prefix ----------
__global__ void __launch_bounds__(HT)
hist_kernel(const float* __restrict__ targets)
{
    __shared__ int h[BINS];
    __shared__ int sa[BINS * HB], sb[BINS * HB];
    __shared__ int last;
    const int tid = threadIdx.x;
    if (tid < BINS) h[tid] = 0;
    __syncthreads();
    const int e = blockIdx.x * HT + tid;
    atomicAdd(&h[dbin(targets[2 * e])], 1);
    __syncthreads();
    if (tid < BINS) g_hist[tid * HB + blockIdx.x] = h[tid];
    __threadfence();
    if (tid == 0) last = (atomicAdd(&g_tick1, 1u) == HB - 1u) ? 1 : 0;
    __syncthreads();
    if (!last) return;
    __threadfence();
    sa[tid]      = g_hist[tid];
    sa[tid + HT] = g_hist[tid + HT];
    __syncthreads();
    int* src = sa; int* dst = sb;
    for (int d = 1; d < BINS * HB; d <<= 1) {
        for (int i = tid; i < BINS * HB; i += HT)
            dst[i] = src[i] + (i >= d ? src[i - d] : 0);
        __syncthreads();
        int* t_ = src; src = dst; dst = t_;
    }
    g_offs[tid]      = (tid == 0) ? 0 : src[tid - 1];
    g_offs[tid + HT] = src[tid + HT - 1];
    if (tid == 0) g_tick1 = 0u;              // reset for next replay
}

// ---------------- kernel 2: deterministic stable scatter ----------------------
__global__ void __launch_bounds__(HT)
scatter_kernel(const float* __restrict__ preds, const float* __restrict__ targets)
{
    __shared__ int cnt[BINS];
    const int tid = threadIdx.x, wid = tid >> 5, lane = tid & 31;
    if (tid < BINS) cnt[tid] = 0;
    __syncthreads();
    const int e = blockIdx.x * HT + tid;
    const float d  = targets[2 * e];
    const float ev = targets[2 * e + 1];
    const float p  = preds[e];
    const int b = dbin(d);
    const unsigned mm = __match_any_sync(0xffffffffu, b);
    const int lrank  = __popc(mm & ((1u << lane) - 1u));
    const int leader = __ffs(mm) - 1;
    int wbase = 0;
    for (int w = 0; w < HT / 32; ++w) {      // serialize warps: stable & deterministic
        if (wid == w) {
            int base = 0;
            if (lane == leader) base = atomicAdd(&cnt[b], __popc(mm));
            wbase = __shfl_sync(0xffffffffu, base, leader);
        }
        __syncthreads();
    }
    const int pos = g_offs[b * HB + blockIdx.x] + wbase + lrank;
    g_sorted[pos] = make_float4(d, p, ev, 0.0f);
}

// ---------------- kernel 3: triangular pair kernel ----------------------------
__global__ void __launch_bounds__(TPB)
pair_kernel(float* __restrict__ out)
{
    __shared__ float4 tile4[JC / 2];         // {dur_2t, p_2t, dur_2t+1, p_2t+1}
    __shared__ float  sdur[IG], scst[IG];
    __shared__ int    wcnt[2 * NW];
    __shared__ float        rs[TPB];
    __shared__ unsigned int rc[TPB];
    __shared__ float  wred[4][NW];
    __shared__ float  bnds[4];               // jmin, jmax, emin, emax
    __shared__ int    last_flag;

    const int tid = threadIdx.x, wid = tid >> 5, lane = tid & 31;
    const int i0 = blockIdx.y * IG + tid;
    const int i1 = i0 + TPB;
    const int j0 = blockIdx.x * JC;

    const float4 r0 = g_sorted[i0];
    const float4 r1 = g_sorted[i1];
    const bool f0 = (r0.z == 1.0f);
    const bool f1 = (r1.z == 1.0f);
    const unsigned bm0 = __ballot_sync(0xffffffffu, f0);
    const unsigned bm1 = __ballot_sync(0xffffffffu, f1);
    if (lane == 0) { wcnt[wid] = __popc(bm0); wcnt[NW + wid] = __popc(bm1); }

    // tile load + j bounds
    float jmn = CUDART_INF_F, jmx = -CUDART_INF_F;
    for (int t = tid; t < JC / 2; t += TPB) {
        const float4 A = g_sorted[j0 + 2 * t];
        const float4 B = g_sorted[j0 + 2 * t + 1];
        tile4[t] = make_float4(A.x, A.y, B.x, B.y);
        jmn = fminf(jmn, fminf(A.x, B.x));
        jmx = fmaxf(jmx, fmaxf(A.x, B.x));
    }
    float emn = fminf(f0 ? r0.x :  CUDART_INF_F, f1 ? r1.x :  CUDART_INF_F);
    float emx = fmaxf(f0 ? r0.x : -CUDART_INF_F, f1 ? r1.x : -CUDART_INF_F);
    #pragma unroll
    for (int o = 16; o > 0; o >>= 1) {
        jmn = fminf(jmn, __shfl_xor_sync(0xffffffffu, jmn, o));
        jmx = fmaxf(jmx, __shfl_xor_sync(0xffffffffu, jmx, o));
        emn = fminf(emn, __shfl_xor_sync(0xffffffffu, emn, o));
        emx = fmaxf(emx, __shfl_xor_sync(0xffffffffu, emx, o));
    }
    if (lane == 0) { wred[0][wid] = jmn; wred[1][wid] = jmx; wred[2][wid] = emn; wred[3][wid] = emx; }
    __syncthreads();
    if (tid == 0) {
        float a = CUDART_INF_F, b = -CUDART_INF_F, c = CUDART_INF_F, d = -CUDART_INF_F;
        #pragma unroll
        for (int w = 0; w < NW; ++w) {
            a = fminf(a, wred[0][w]); b = fmaxf(b, wred[1][w]);
            c = fminf(c, wred[2][w]); d = fmaxf(d, wred[3][w]);
        }
        bnds[0] = a; bnds[1] = b; bnds[2] = c; bnds[3] = d;
    }

    // order-preserving compaction (prefix over 16 warp counts)
    int base0 = 0, base1 = 0, m = 0;
    #pragma unroll
    for (int w = 0; w < NW; ++w) {
        const int c = wcnt[w];
        if (w < wid) base0 += c;
        base1 += c;
        m += c;
    }
    #pragma unroll
    for (int w = 0; w < NW; ++w) {
        const int c = wcnt[NW + w];
        if (w < wid) base1 += c;
        m += c;
    }
    if (f0) {
        const int pos = base0 + __popc(bm0 & ((1u << lane) - 1u));
        sdur[pos] = r0.x; scst[pos] = 1.0f - r0.y;
    }
    if (f1) {
        const int pos = base1 + __popc(bm1 & ((1u << lane) - 1u));
        sdur[pos] = r1.x; scst[pos] = 1.0f - r1.y;
    }
    __syncthreads();

    const float jminv = bnds[0], jmaxv = bnds[1];
    const float eminv = bnds[2], emaxv = bnds[3];
    const bool skip = (m == 0) || (jmaxv <= eminv);   // all pairs invalid
    const bool full = (jminv > emaxv);                // all pairs valid

    float s0 = 0.0f, s1 = 0.0f, s2 = 0.0f, s3 = 0.0f;
    unsigned int cnt = 0u;
    if (!skip) {
        if (full) {
            for (int r = tid; r < m; r += TPB) {
                const float c = scst[r];
                cnt += JC;
                #pragma unroll 4
                for (int t = 0; t < JC / 2; t += 2) {
                    const float4 A = tile4[t];
                    const float4 B = tile4[t + 1];
                    s0 += fmaxf(c + A.y, 0.0f);
                    s1 += fmaxf(c + A.w, 0.0f);
                    s2 += fmaxf(c + B.y, 0.0f);
                    s3 += fmaxf(c + B.w, 0.0f);
                }
            }
        } else {
            for (int r = tid; r < m; r += TPB) {
                const float dur = sdur[r];
                const float c   = scst[r];
                #pragma unroll 4
                for (int t = 0; t < JC / 2; t += 2) {
                    const float4 A = tile4[t];
                    const float4 B = tile4[t + 1];
                    if (dur < A.x) { s0 += fmaxf(c + A.y, 0.0f); cnt++; }
                    if (dur < A.z) { s1 += fmaxf(c + A.w, 0.0f); cnt++; }
                    if (dur < B.x) { s2 += fmaxf(c + B.y, 0.0f); cnt++; }
                    if (dur < B.z) { s3 += fmaxf(c + B.w, 0.0f); cnt++; }
                }
            }
        }
    }

    // deterministic block reduction
    rs[tid] = (s0 + s1) + (s2 + s3);
    rc[tid] = cnt;
    __syncthreads();
    #pragma unroll
    for (int o = TPB / 2; o > 0; o >>= 1) {
        if (tid < o) { rs[tid] += rs[tid + o]; rc[tid] += rc[tid + o]; }
        __syncthreads();
    }

    if (tid == 0) {
        const int slot = blockIdx.y * GX + blockIdx.x;
        g_s[slot] = rs[0];
        g_c[slot] = rc[0];
        __threadfence();
        last_flag = (atomicAdd(&g_tick2, 1u) == NBLK - 1u) ? 1 : 0;
    }
    __syncthreads();

    if (last_flag) {
        __threadfence();
        rs[tid] = (g_s[tid] + g_s[tid + TPB]) + (g_s[tid + 2 * TPB] + g_s[tid + 3 * TPB]);
        rc[tid] = (g_c[tid] + g_c[tid + TPB]) + (g_c[tid + 2 * TPB] + g_c[tid + 3 * TPB]);
        __syncthreads();
        #pragma unroll
        for (int o = TPB / 2; o > 0; o >>= 1) {
            if (tid < o) { rs[tid] += rs[tid + o]; rc[tid] += rc[tid + o]; }
            __syncthreads();
        }
        if (tid == 0) {
            out[0] = (rc[0] > 0u) ? (rs[0] / (float)rc[0]) : 0.0f;
            g_tick2 = 0u;                    // reset for next replay
        }
    }
}

extern "C" void kernel_launch(void* const* d_in, const int* in_sizes, int n_in,
                              void* d_out, int out_size)
{
    const float* preds   = (const float*)d_in[0];   // [8192]
    const float* targets = (const float*)d_in[1];   // [8192,2] {dur, ev}
    float* out = (float*)d_out;

    hist_kernel<<<HB, HT>>>(targets);
    scatter_kernel<<<HB, HT>>>(preds, targets);
    dim3 grid(GX, GYI);
    pair_kernel<<<grid, TPB>>>(out);
}

// round 9
// speedup vs baseline: 1.0213x; 1.0213x over previous
#include <cuda_runtime.h>
#include <math_constants.h>

// RankingLoss over all pairs, N=8192.
// loss = sum_{i,j: dur_i<dur_j, ev_i==1} max(1-(p_i-p_j),0) / count (0 if count==0).
//
// (1) histogram by 64 duration bins + cheap structured prefix (last block),
// (2) deterministic STABLE counting-sort scatter (parallel warp-rank, no serialization),
// (3) tiled pair kernel on the sorted array with runtime full/skip/compare
//     classification per block (correct for ANY permutation; the sort makes ~half
//     the blocks skip and most of the rest take the 3-instr/pair full path).

#define NN   8192
#define BINS 64
#define HB   16                  // histogram/scatter blocks
#define HT   512                 // their threads
#define HWN  (HT / 32)           // 16 warps
#define TPB  256
#define IG   512                 // i-rows per pair-block
#define JC   128                 // j-cols per pair-block
#define GX   (NN / JC)           // 64
#define GYI  (NN / IG)           // 16
#define NBLK (GX * GYI)          // 1024
#define NW   (TPB / 32)

__device__ float4       g_sorted[NN];        // {dur, pred, event, 0} duration-ordered
__device__ int          g_hist[BINS * HB];   // [bin][block]
__device__ int          g_offs[BINS * HB];   // [bin][block] global exclusive offsets
__device__ float        g_s[NBLK];
__device__ unsigned int g_c[NBLK];
__device__ unsigned int g_tick1 = 0u;
__device__ unsigned int g_tick2 = 0u;

__device__ __forceinline__ int dbin(float d) {
    int b = (int)(d * (float)BINS);          // monotone in d (uniform [0,1) data)
    return b < 0 ? 0 : (b > BINS - 1 ? BINS - 1 : b);
}

// ---------------- kernel 1: histogram + structured prefix (last block) --------
__global__ void __launch_bounds__(HT)
hist_kernel(const float* __restrict__ targets)
{
    __shared__ int h[BINS];
    __shared__ int sh[BINS * HB];
    __shared__ int bt[BINS];
    __shared__ int last;
    const int tid = threadIdx.x;
    if (tid < BINS) h[tid] = 0;
    __syncthreads();
    const int e = blockIdx.x * HT + tid;
    atomicAdd(&h[dbin(targets[2 * e])], 1);
    __syncthreads();
    if (tid < BINS) g_hist[tid * HB + blockIdx.x] = h[tid];
    __threadfence();
    if (tid == 0) last = (atomicAdd(&g_tick1, 1u) == HB - 1u) ? 1 : 0;
    __syncthreads();
    if (!last) return;
    __threadfence();

    sh[tid]      = g_hist[tid];
    sh[tid + HT] = g_hist[tid + HT];
    __syncthreads();
    if (tid < BINS) {                        // per-bin totals (16 adds each)
        int s = 0;
        #pragma unroll
        for (int k = 0; k < HB; ++k) s += sh[tid * HB + k];
        bt[tid] = s;
    }
    __syncthreads();
    if (tid == 0) {                          // exclusive prefix over 64 bins
        int acc = 0;
        #pragma unroll
        for (int b = 0; b < BINS; ++b) { const int v = bt[b]; bt[b] = acc; acc += v; }
    }
    __syncthreads();
    #pragma unroll
    for (int idx = tid; idx < BINS * HB; idx += HT) {   // 2 slots/thread, <=15 adds
        const int b = idx / HB, k = idx % HB;
        int s = bt[b];
        for (int kk = 0; kk < k; ++kk) s += sh[b * HB + kk];
        g_offs[idx] = s;
    }
    if (tid == 0) g_tick1 = 0u;              // reset for next replay
}

// ---------------- kernel 2: deterministic stable scatter (parallel rank) ------
__global__ void __launch_bounds__(HT)
scatter_kernel(const float* __restrict__ preds, const float* __restrict__ targets)
{
    __shared__ int wc[HWN][BINS];            // per-warp per-bin counts
    const int tid = threadIdx.x, wid = tid >> 5, lane = tid & 31;
    for (int idx = tid; idx < HWN * BINS; idx += HT) ((int*)wc)[idx] = 0;
    __syncthreads();
    const int e = blockIdx.x * HT + tid;
    const float2 tg = ((const float2*)targets)[e];
    const float  p  = preds[e];
    const int b = dbin(tg.x);
    const unsigned mm = __match_any_sync(0xffffffffu, b);
    const int lrank = __popc(mm & ((1u << lane) - 1u));
    if (lrank == 0) wc[wid][b] = __popc(mm);     // leader writes group size
    __syncthreads();
    int base = 0;
    for (int w = 0; w < HWN; ++w) if (w < wid) base += wc[w][b];
    const int pos = g_offs[b * HB + blockIdx.x] + base + lrank;
    g_sorted[pos] = make_float4(tg.x, p, tg.y, 0.0f);   // stable: block/warp/lane-major
}

// ---------------- kernel 3: triangular pair kernel ----------------------------
__global__ void __launch_bounds__(TPB)
pair_kernel(float* __restrict__ out)
{
    __shared__ float4 tile4[JC / 2];         // {dur_2t, p_2t, dur_2t+1, p_2t+1}
    __shared__ float  sdur[IG], scst[IG];
    __shared__ int    wcnt[2 * NW];
    __shared__ float        rs[TPB];
    __shared__ unsigned int rc[TPB];
    __shared__ float  wred[4][NW];
    __shared__ float  bnds[4];               // jmin, jmax, emin, emax
    __shared__ int    last_flag;

    const int tid = threadIdx.x, wid = tid >> 5, lane = tid & 31;
    const int i0 = blockIdx.y * IG + tid;
    const int i1 = i0 + TPB;
    const int j0 = blockIdx.x * JC;

    const float4 r0 = g_sorted[i0];
    const float4 r1 = g_sorted[i1];
    const bool f0 = (r0.z == 1.0f);
    const bool f1 = (r1.z == 1.0f);
    const unsigned bm0 = __ballot_sync(0xffffffffu, f0);
    const unsigned bm1 = __ballot_sync(0xffffffffu, f1);
    if (lane == 0) { wcnt[wid] = __popc(bm0); wcnt[NW + wid] = __popc(bm1); }

    // tile load + honest j bounds (correct for any permutation)
    float jmn = CUDART_INF_F, jmx = -CUDART_INF_F;
    for (int t = tid; t < JC / 2; t += TPB) {
        const float4 A = g_sorted[j0 + 2 * t];
        const float4 B = g_sorted[j0 + 2 * t + 1];
        tile4[t] = make_float4(A.x, A.y, B.x, B.y);
        jmn = fminf(jmn, fminf(A.x, B.x));
        jmx = fmaxf(jmx, fmaxf(A.x, B.x));
    }
    float emn = fminf(f0 ? r0.x :  CUDART_INF_F, f1 ? r1.x :  CUDART_INF_F);
    float emx = fmaxf(f0 ? r0.x : -CUDART_INF_F, f1 ? r1.x : -CUDART_INF_F);
    #pragma unroll
    for (int o = 16; o > 0; o >>= 1) {
        jmn = fminf(jmn, __shfl_xor_sync(0xffffffffu, jmn, o));
        jmx = fmaxf(jmx, __shfl_xor_sync(0xffffffffu, jmx, o));
        emn = fminf(emn, __shfl_xor_sync(0xffffffffu, emn, o));
        emx = fmaxf(emx, __shfl_xor_sync(0xffffffffu, emx, o));
    }
    if (lane == 0) { wred[0][wid] = jmn; wred[1][wid] = jmx; wred[2][wid] = emn; wred[3][wid] = emx; }
    __syncthreads();
    if (tid == 0) {
        float a = CUDART_INF_F, b = -CUDART_INF_F, c = CUDART_INF_F, d = -CUDART_INF_F;
        #pragma unroll
        for (int w = 0; w < NW; ++w) {
            a = fminf(a, wred[0][w]); b = fmaxf(b, wred[1][w]);
            c = fminf(c, wred[2][w]); d = fmaxf(d, wred[3][w]);
        }
        bnds[0] = a; bnds[1] = b; bnds[2] = c; bnds[3] = d;
    }

    // order-preserving compaction (prefix over 16 warp counts)
    int base0 = 0, base1 = 0, m = 0;
    #pragma unroll
    for (int w = 0; w < NW; ++w) {
        const int c = wcnt[w];
        if (w < wid) base0 += c;
        base1 += c;
        m += c;
    }
    #pragma unroll
    for (int w = 0; w < NW; ++w) {
        const int c = wcnt[NW + w];
        if (w < wid) base1 += c;
        m += c;
    }
    if (f0) {
        const int pos = base0 + __popc(bm0 & ((1u << lane) - 1u));
        sdur[pos] = r0.x; scst[pos] = 1.0f - r0.y;
    }
    if (f1) {
        const int pos = base1 + __popc(bm1 & ((1u << lane) - 1u));
        sdur[pos] = r1.x; scst[pos] = 1.0f - r1.y;
    }
    __syncthreads();

    const bool skip = (m == 0) || (bnds[1] <= bnds[2]);   // all pairs invalid
    const bool full = (bnds[0] > bnds[3]);                // all pairs valid

    float s0 = 0.0f, s1 = 0.0f, s2 = 0.0f, s3 = 0.0f;
    unsigned int cnt = 0u;
    if (!skip) {
        if (full) {
            for (int r = tid; r < m; r += TPB) {
                const float c = scst[r];
                cnt += JC;
                #pragma unroll 4
                for (int t = 0; t < JC / 2; t += 2) {
                    const float4 A = tile4[t];
                    const float4 B = tile4[t + 1];
                    s0 += fmaxf(c + A.y, 0.0f);
                    s1 += fmaxf(c + A.w, 0.0f);
                    s2 += fmaxf(c + B.y, 0.0f);
                    s3 += fmaxf(c + B.w, 0.0f);
                }
            }
        } else {
            for (int r = tid; r < m; r += TPB) {
                const float dur = sdur[r];
                const float c   = scst[r];
                #pragma unroll 4
                for (int t = 0; t < JC / 2; t += 2) {
                    const float4 A = tile4[t];
                    const float4 B = tile4[t + 1];
                    if (dur < A.x) { s0 += fmaxf(c + A.y, 0.0f); cnt++; }
                    if (dur < A.z) { s1 += fmaxf(c + A.w, 0.0f); cnt++; }
                    if (dur < B.x) { s2 += fmaxf(c + B.y, 0.0f); cnt++; }
                    if (dur < B.z) { s3 += fmaxf(c + B.w, 0.0f); cnt++; }
                }
            }
        }
    }

    // deterministic block reduction
    rs[tid] = (s0 + s1) + (s2 + s3);
    rc[tid] = cnt;
    __syncthreads();
    #pragma unroll
    for (int o = TPB / 2; o > 0; o >>= 1) {
        if (tid < o) { rs[tid] += rs[tid + o]; rc[tid] += rc[tid + o]; }
        __syncthreads();
    }

    if (tid == 0) {
        const int slot = blockIdx.y * GX + blockIdx.x;
        g_s[slot] = rs[0];
        g_c[slot] = rc[0];
        __threadfence();
        last_flag = (atomicAdd(&g_tick2, 1u) == NBLK - 1u) ? 1 : 0;
    }
    __syncthreads();

    if (last_flag) {
        __threadfence();
        rs[tid] = (g_s[tid] + g_s[tid + TPB]) + (g_s[tid + 2 * TPB] + g_s[tid + 3 * TPB]);
        rc[tid] = (g_c[tid] + g_c[tid + TPB]) + (g_c[tid + 2 * TPB] + g_c[tid + 3 * TPB]);
        __syncthreads();
        #pragma unroll
        for (int o = TPB / 2; o > 0; o >>= 1) {
            if (tid < o) { rs[tid] += rs[tid + o]; rc[tid] += rc[tid + o]; }
            __syncthreads();
        }
        if (tid == 0) {
            out[0] = (rc[0] > 0u) ? (rs[0] / (float)rc[0]) : 0.0f;
            g_tick2 = 0u;                    // reset for next replay
        }
    }
}

extern "C" void kernel_launch(void* const* d_in, const int* in_sizes, int n_in,
                              void* d_out, int out_size)
{
    const float* preds   = (const float*)d_in[0];   // [8192]
    const float* targets = (const float*)d_in[1];   // [8192,2] {dur, ev}
    float* out = (float*)d_out;

    hist_kernel<<<HB, HT>>>(targets);
    scatter_kernel<<<HB, HT>>>(preds, targets);
    dim3 grid(GX, GYI);
    pair_kernel<<<grid, TPB>>>(out);
}

// round 10
// speedup vs baseline: 1.0227x; 1.0014x over previous
#include <cuda_runtime.h>

// RankingLoss over all pairs, N=8192.
// loss = sum_{i,j: dur_i<dur_j, ev_i==1} max(1-(p_i-p_j),0) / count (0 if count==0).
//
// Kernel 1 (prep, 16 blocks, single launch): duration histogram (64 bins) ->
//   global tick -> last block computes exclusive offsets -> releases a flag ->
//   all (resident) blocks spin on the flag -> deterministic STABLE counting-sort
//   scatter into g_srt {dur, pred, event, 0} (bin-sorted by duration).
// Kernel 2 (pair): grid (64 j-chunks x 16 i-groups). Because g_srt is bin-sorted,
//   block classification is 4 loads + bin compares: skip (~47% of blocks, exit in
//   ~30 instr), full (no compare, preds-only inner loop, 3.5 slots/pair), or
//   exact-compare (bin-straddling blocks; handles ties). Last-arriving block
//   reduces all partials in fixed order. Everything is deterministic.

#define NN   8192
#define BINS 64
#define PB   16                  // prep blocks (always co-resident -> spin is safe)
#define PT   512                 // prep threads
#define PWN  (PT / 32)           // 16 warps
#define TPB  256
#define IG   512                 // i-rows per pair-block
#define JC   128                 // j-cols per pair-block
#define GX   (NN / JC)           // 64
#define GYI  (NN / IG)           // 16
#define NBLK (GX * GYI)          // 1024
#define NW   (TPB / 32)

__device__ float4       g_srt[NN];           // {dur, pred, event, 0} bin-sorted by dur
__device__ int          g_hist[BINS * PB];   // [bin][block]
__device__ int          g_offs[BINS * PB];   // [bin][block] global exclusive offsets
__device__ float        g_s[NBLK];
__device__ unsigned int g_c[NBLK];
__device__ int          g_flag  = 0;
__device__ unsigned int g_tickA = 0u;
__device__ unsigned int g_tickB = 0u;
__device__ unsigned int g_tickP = 0u;

__device__ __forceinline__ int dbin(float d) {
    int b = (int)(d * (float)BINS);          // monotone in d
    return b < 0 ? 0 : (b > BINS - 1 ? BINS - 1 : b);
}

// ---------------- kernel 1: fused hist + offsets + stable scatter -------------
__global__ void __launch_bounds__(PT)
prep_kernel(const float* __restrict__ preds, const float* __restrict__ targets)
{
    __shared__ int wc[PWN][BINS];            // per-warp per-bin counts
    __shared__ int sh[BINS * PB];            // last block: all hists
    __shared__ int bt[BINS];                 // last block: bin bases
    __shared__ int is_last;

    const int tid = threadIdx.x, wid = tid >> 5, lane = tid & 31;
    for (int idx = tid; idx < PWN * BINS; idx += PT) ((int*)wc)[idx] = 0;
    __syncthreads();

    const int   e  = blockIdx.x * PT + tid;
    const float2 tg = ((const float2*)targets)[e];
    const float  p  = preds[e];
    const int    b  = dbin(tg.x);
    const unsigned mm   = __match_any_sync(0xffffffffu, b);
    const int      lr   = __popc(mm & ((1u << lane) - 1u));
    if (lr == 0) wc[wid][b] = __popc(mm);    // leader writes group size
    __syncthreads();

    if (tid < BINS) {                        // per-block bin totals (no atomics)
        int s = 0;
        #pragma unroll
        for (int w = 0; w < PWN; ++w) s += wc[w][tid];
        g_hist[tid * PB + blockIdx.x] = s;
    }
    __threadfence();
    if (tid == 0) is_last = (atomicAdd(&g_tickP, 1u) == PB - 1u) ? 1 : 0;
    __syncthreads();

    if (is_last) {
        __threadfence();
        sh[tid]      = g_hist[tid];
        sh[tid + PT] = g_hist[tid + PT];
        __syncthreads();
        if (tid < BINS) {                    // bin totals across blocks
            int s = 0;
            #pragma unroll
            for (int k = 0; k < PB; ++k) s += sh[tid * PB + k];
            bt[tid] = s;
        }
        __syncthreads();
        if (tid == 0) {                      // exclusive prefix over 64 bins
            int acc = 0;
            #pragma unroll
            for (int bb = 0; bb < BINS; ++bb) { const int v = bt[bb]; bt[bb] = acc; acc += v; }
        }
        __syncthreads();
        for (int idx = tid; idx < BINS * PB; idx += PT) {
            const int bb = idx / PB, k = idx % PB;
            int s = bt[bb];
            for (int kk = 0; kk < k; ++kk) s += sh[bb * PB + kk];
            g_offs[idx] = s;
        }
        __threadfence();
        if (tid == 0) atomicExch(&g_flag, 1);    // release
    }

    // all blocks wait for offsets (PB blocks are always co-resident)
    if (tid == 0) {
        while (atomicAdd(&g_flag, 0) == 0) __nanosleep(64);
    }
    __syncthreads();
    __threadfence();                         // acquire

    // stable scatter: block-major / warp-major / lane-major == original order
    int base = 0;
    for (int w = 0; w < wid; ++w) base += wc[w][b];
    const int pos = g_offs[b * PB + blockIdx.x] + base + lr;
    g_srt[pos] = make_float4(tg.x, p, tg.y, 0.0f);

    // replay cleanup (after every block has passed the flag)
    __threadfence();
    if (tid == 0 && atomicAdd(&g_tickA, 1u) == PB - 1u) {
        g_flag = 0; g_tickP = 0u; g_tickA = 0u;
    }
}

// ---------------- kernel 2: classified pair kernel ----------------------------
__global__ void __launch_bounds__(TPB)
pair_kernel(float* __restrict__ out)
{
    __shared__ float  sdj[JC], spj[JC];      // j durs / j preds
    __shared__ float  sdur[IG], scst[IG];    // compacted events
    __shared__ int    wcnt[2 * NW];
    __shared__ float  cls[4];                // i_first, i_last, j_first, j_last durs
    __shared__ float        rs[TPB];
    __shared__ unsigned int rc[TPB];
    __shared__ int    last_flag;

    const int tid = threadIdx.x, wid = tid >> 5, lane = tid & 31;
    const int ib = blockIdx.y * IG;
    const int j0 = blockIdx.x * JC;

    if (tid < 4) {
        const int idx = (tid == 0) ? ib : (tid == 1) ? (ib + IG - 1)
                      : (tid == 2) ? j0 : (j0 + JC - 1);
        cls[tid] = g_srt[idx].x;
    }
    __syncthreads();
    const int biF = dbin(cls[0]), biL = dbin(cls[1]);
    const int bjF = dbin(cls[2]), bjL = dbin(cls[3]);
    const bool skip = (bjL < biF);           // all j-durs < all i-durs -> no valid pair
    const bool full = (bjF > biL);           // all j-durs > all i-durs -> all pairs valid

    float s0 = 0.0f, s1 = 0.0f, s2 = 0.0f, s3 = 0.0f;
    unsigned int cnt = 0u;

    if (!skip) {
        // i-rows + ballot compaction (order-preserving, deterministic)
        const float4 r0 = g_srt[ib + tid];
        const float4 r1 = g_srt[ib + TPB + tid];
        const bool f0 = (r0.z == 1.0f);
        const bool f1 = (r1.z == 1.0f);
        const unsigned bm0 = __ballot_sync(0xffffffffu, f0);
        const unsigned bm1 = __ballot_sync(0xffffffffu, f1);
        if (lane == 0) { wcnt[wid] = __popc(bm0); wcnt[NW + wid] = __popc(bm1); }

        for (int t = tid; t < JC; t += TPB) {    // j tile (split arrays)
            const float4 J = g_srt[j0 + t];
            sdj[t] = J.x;
            spj[t] = J.y;
        }
        __syncthreads();

        int base0 = 0, base1 = 0, m = 0;
        #pragma unroll
        for (int w = 0; w < NW; ++w) {
            const int c = wcnt[w];
            if (w < wid) base0 += c;
            base1 += c;
            m += c;
        }
        #pragma unroll
        for (int w = 0; w < NW; ++w) {
            const int c = wcnt[NW + w];
            if (w < wid) base1 += c;
            m += c;
        }
        if (f0) {
            const int pos = base0 + __popc(bm0 & ((1u << lane) - 1u));
            sdur[pos] = r0.x; scst[pos] = 1.0f - r0.y;
        }
        if (f1) {
            const int pos = base1 + __popc(bm1 & ((1u << lane) - 1u));
            sdur[pos] = r1.x; scst[pos] = 1.0f - r1.y;
        }
        __syncthreads();

        if (full) {
            for (int r = tid; r < m; r += TPB) {
                const float c = scst[r];
                cnt += JC;
                const float4* sp4 = (const float4*)spj;
                #pragma unroll 8
                for (int t = 0; t < JC / 4; ++t) {
                    const float4 P = sp4[t];
                    s0 += fmaxf(c + P.x, 0.0f);
                    s1 += fmaxf(c + P.y, 0.0f);
                    s2 += fmaxf(c + P.z, 0.0f);
                    s3 += fmaxf(c + P.w, 0.0f);
                }
            }
        } else {
            for (int r = tid; r < m; r += TPB) {
                const float dur = sdur[r];
                const float c   = scst[r];
                const float4* sd4 = (const float4*)sdj;
                const float4* sp4 = (const float4*)spj;
                #pragma unroll 4
                for (int t = 0; t < JC / 4; ++t) {
                    const float4 D = sd4[t];
                    const float4 P = sp4[t];
                    if (dur < D.x) { s0 += fmaxf(c + P.x, 0.0f); cnt++; }
                    if (dur < D.y) { s1 += fmaxf(c + P.y, 0.0f); cnt++; }
                    if (dur < D.z) { s2 += fmaxf(c + P.z, 0.0f); cnt++; }
                    if (dur < D.w) { s3 += fmaxf(c + P.w, 0.0f); cnt++; }
                }
            }
        }
    }

    // deterministic block reduction (skip blocks contribute zeros)
    rs[tid] = (s0 + s1) + (s2 + s3);
    rc[tid] = cnt;
    __syncthreads();
    #pragma unroll
    for (int o = TPB / 2; o > 0; o >>= 1) {
        if (tid < o) { rs[tid] += rs[tid + o]; rc[tid] += rc[tid + o]; }
        __syncthreads();
    }

    if (tid == 0) {
        const int slot = blockIdx.y * GX + blockIdx.x;
        g_s[slot] = rs[0];
        g_c[slot] = rc[0];
        __threadfence();
        last_flag = (atomicAdd(&g_tickB, 1u) == NBLK - 1u) ? 1 : 0;
    }
    __syncthreads();

    if (last_flag) {
        __threadfence();
        rs[tid] = (g_s[tid] + g_s[tid + TPB]) + (g_s[tid + 2 * TPB] + g_s[tid + 3 * TPB]);
        rc[tid] = (g_c[tid] + g_c[tid + TPB]) + (g_c[tid + 2 * TPB] + g_c[tid + 3 * TPB]);
        __syncthreads();
        #pragma unroll
        for (int o = TPB / 2; o > 0; o >>= 1) {
            if (tid < o) { rs[tid] += rs[tid + o]; rc[tid] += rc[tid + o]; }
            __syncthreads();
        }
        if (tid == 0) {
            out[0] = (rc[0] > 0u) ? (rs[0] / (float)rc[0]) : 0.0f;
            g_tickB = 0u;                    // reset for next replay
        }
    }
}

extern "C" void kernel_launch(void* const* d_in, const int* in_sizes, int n_in,
                              void* d_out, int out_size)
{
    const float* preds   = (const float*)d_in[0];   // [8192]
    const float* targets = (const float*)d_in[1];   // [8192,2] {dur, ev}
    float* out = (float*)d_out;

    prep_kernel<<<PB, PT>>>(preds, targets);
    dim3 grid(GX, GYI);
    pair_kernel<<<grid, TPB>>>(out);
}